// round 1
// baseline (speedup 1.0000x reference)
#include <cuda_runtime.h>

// SCC (sliding channel conv): out[b,o,p] = sum_j w[o,j] * x[b, (o*128+j)&1023, p]
// Decomposes into 8 independent GEMMs by group r = o % 8:
//   out[r + 8m, p] = sum_k W[r+8m, k] * x[(128r + k) & 1023, p]
// per batch b. M=128 rows/group, K=256, N=3136 spatial per batch.

#define BATCH   16
#define C_IN    1024
#define HW      3136
#define C_OUT   1024
#define UNIT    256
#define STRIDE  128
#define NGRP    8            // C_IN / STRIDE
#define MROWS   128          // C_OUT / NGRP
#define TILE_N  128
#define TILE_K  16
#define NKT     (UNIT / TILE_K)   // 16
#define APAD    132          // padded A row to kill STS bank conflicts

__global__ __launch_bounds__(256, 2)
void scc_sgemm_kernel(const float* __restrict__ x,
                      const float* __restrict__ w,
                      float* __restrict__ out)
{
    __shared__ float As[2][TILE_K][APAD];    // [k][m], padded
    __shared__ float Bs[2][TILE_K][TILE_N];  // [k][p]

    const int tid   = threadIdx.x;
    const int ntile = blockIdx.x;   // spatial tile
    const int r     = blockIdx.y;   // group (o mod 8)
    const int b     = blockIdx.z;   // batch

    const int p0 = ntile * TILE_N;
    const float* xb = x + (size_t)b * C_IN * HW;
    float*       ob = out + (size_t)b * C_OUT * HW;
    const int cbase = r * STRIDE;

    // micro-tile coordinates: 16x16 thread grid, 8x8 per thread
    const int tx = tid & 15;       // N
    const int ty = tid >> 4;       // M
    const int m0 = ty * 8;
    const int n0 = tx * 8;

    float acc[8][8];
    #pragma unroll
    for (int i = 0; i < 8; i++)
        #pragma unroll
        for (int j = 0; j < 8; j++) acc[i][j] = 0.f;

    float4 aReg[2], bReg[2];

    // ---- loader lambda-equivalents (manually inlined) ----
    // A: i = tid + 256*it ; m = i>>2 (0..127), kq = i&3 (0..3) -> 4 k-floats
    // B: i = tid + 256*it ; kk = i>>5 (0..15), pq = i&31 -> 4 p-floats

    // prologue: stage k-tile 0
    {
        const int k0 = 0;
        #pragma unroll
        for (int it = 0; it < 2; it++) {
            const int i = tid + 256 * it;
            const int m  = i >> 2, kq = i & 3;
            aReg[it] = *(const float4*)(w + (size_t)(r + 8 * m) * UNIT + k0 + kq * 4);
            const int kk = i >> 5, pq = i & 31;
            const int c = (cbase + k0 + kk) & (C_IN - 1);
            const int p = p0 + pq * 4;
            bReg[it] = (p < HW) ? *(const float4*)(xb + (size_t)c * HW + p)
                                : make_float4(0.f, 0.f, 0.f, 0.f);
        }
        #pragma unroll
        for (int it = 0; it < 2; it++) {
            const int i = tid + 256 * it;
            const int m  = i >> 2, kq = i & 3;
            As[0][kq * 4 + 0][m] = aReg[it].x;
            As[0][kq * 4 + 1][m] = aReg[it].y;
            As[0][kq * 4 + 2][m] = aReg[it].z;
            As[0][kq * 4 + 3][m] = aReg[it].w;
            const int kk = i >> 5, pq = i & 31;
            *(float4*)&Bs[0][kk][pq * 4] = bReg[it];
        }
    }
    __syncthreads();

    for (int kt = 0; kt < NKT; kt++) {
        const int cur = kt & 1;

        // prefetch next k-tile into registers (overlaps with compute)
        if (kt + 1 < NKT) {
            const int k0 = (kt + 1) * TILE_K;
            #pragma unroll
            for (int it = 0; it < 2; it++) {
                const int i = tid + 256 * it;
                const int m  = i >> 2, kq = i & 3;
                aReg[it] = *(const float4*)(w + (size_t)(r + 8 * m) * UNIT + k0 + kq * 4);
                const int kk = i >> 5, pq = i & 31;
                const int c = (cbase + k0 + kk) & (C_IN - 1);
                const int p = p0 + pq * 4;
                bReg[it] = (p < HW) ? *(const float4*)(xb + (size_t)c * HW + p)
                                    : make_float4(0.f, 0.f, 0.f, 0.f);
            }
        }

        // compute on current buffer
        #pragma unroll
        for (int kk = 0; kk < TILE_K; kk++) {
            float a[8], bb[8];
            *(float4*)&a[0]  = *(const float4*)&As[cur][kk][m0];
            *(float4*)&a[4]  = *(const float4*)&As[cur][kk][m0 + 4];
            *(float4*)&bb[0] = *(const float4*)&Bs[cur][kk][n0];
            *(float4*)&bb[4] = *(const float4*)&Bs[cur][kk][n0 + 4];
            #pragma unroll
            for (int i = 0; i < 8; i++)
                #pragma unroll
                for (int j = 0; j < 8; j++)
                    acc[i][j] = fmaf(a[i], bb[j], acc[i][j]);
        }

        // stage next buffer
        if (kt + 1 < NKT) {
            const int nxt = cur ^ 1;
            #pragma unroll
            for (int it = 0; it < 2; it++) {
                const int i = tid + 256 * it;
                const int m  = i >> 2, kq = i & 3;
                As[nxt][kq * 4 + 0][m] = aReg[it].x;
                As[nxt][kq * 4 + 1][m] = aReg[it].y;
                As[nxt][kq * 4 + 2][m] = aReg[it].z;
                As[nxt][kq * 4 + 3][m] = aReg[it].w;
                const int kk = i >> 5, pq = i & 31;
                *(float4*)&Bs[nxt][kk][pq * 4] = bReg[it];
            }
            __syncthreads();
        }
    }

    // store 8x8 micro-tile; out channel = r + 8*(m0+im), spatial = p0+n0+..
    #pragma unroll
    for (int im = 0; im < 8; im++) {
        const int o = r + 8 * (m0 + im);
        float* orow = ob + (size_t)o * HW + p0 + n0;
        if (p0 + n0 + 3 < HW) {
            *(float4*)orow = make_float4(acc[im][0], acc[im][1], acc[im][2], acc[im][3]);
        }
        if (p0 + n0 + 7 < HW) {
            *(float4*)(orow + 4) = make_float4(acc[im][4], acc[im][5], acc[im][6], acc[im][7]);
        }
    }
}

extern "C" void kernel_launch(void* const* d_in, const int* in_sizes, int n_in,
                              void* d_out, int out_size)
{
    const float* x = (const float*)d_in[0];
    const float* w = (const float*)d_in[1];
    // d_in[2] = overlap (int scalar) -- fixed at 128 for this problem shape.
    float* out = (float*)d_out;

    dim3 grid((HW + TILE_N - 1) / TILE_N, NGRP, BATCH);  // 25 x 8 x 16
    scc_sgemm_kernel<<<grid, 256>>>(x, w, out);
}

// round 3
// speedup vs baseline: 1.9679x; 1.9679x over previous
#include <cuda_runtime.h>
#include <cstdint>

#define HW   3136
#define CIN  1024
#define UNIT 256
#define NT   128
#define KC   32
#define NCH  8          // 256 / 32
#define PM   136        // smem pitch (floats) for [k][m] and [k][n] tiles
#define EP   132        // epilogue staging pitch (floats)

#define AS_OFF 0
#define BS_OFF (2 * KC * PM)         // float offset of B buffers
#define SM_BYTES (4 * KC * PM * 4)   // 69632 bytes (2xA + 2xB stage buffers)

static __device__ __forceinline__ float rna_f(float v) {
    uint32_t o;
    asm("cvt.rna.tf32.f32 %0, %1;" : "=r"(o) : "f"(v));
    return __uint_as_float(o);
}

static __device__ __forceinline__ void mma8(float* c, const float* a, const float* b) {
    asm volatile(
        "mma.sync.aligned.m16n8k8.row.col.f32.tf32.tf32.f32 "
        "{%0,%1,%2,%3}, {%4,%5,%6,%7}, {%8,%9}, {%0,%1,%2,%3};"
        : "+f"(c[0]), "+f"(c[1]), "+f"(c[2]), "+f"(c[3])
        : "r"(__float_as_uint(a[0])), "r"(__float_as_uint(a[1])),
          "r"(__float_as_uint(a[2])), "r"(__float_as_uint(a[3])),
          "r"(__float_as_uint(b[0])), "r"(__float_as_uint(b[1])));
}

__global__ __launch_bounds__(256, 1)
void scc_mma_kernel(const float* __restrict__ x,
                    const float* __restrict__ w,
                    float* __restrict__ out)
{
    extern __shared__ float sm[];
    const int tid = threadIdx.x;
    const int lid = tid & 31, wid = tid >> 5;
    const int g = lid >> 2, tg = lid & 3;        // mma quad coords
    const int r  = blockIdx.x;                   // group (o mod 8), fastest -> L2 x reuse
    const int p0 = blockIdx.y * NT;              // spatial tile
    const int b  = blockIdx.z;                   // batch
    const float* xb = x + (size_t)b * CIN * HW;

    const int m0 = (wid & 1) * 64;               // warp M offset (2x4 warp grid)
    const int n0 = (wid >> 1) * 32;              // warp N offset

    float acc[4][4][4];
    #pragma unroll
    for (int i = 0; i < 4; i++)
        #pragma unroll
        for (int j = 0; j < 4; j++)
            #pragma unroll
            for (int v = 0; v < 4; v++) acc[i][j][v] = 0.f;

    // loader thread roles (flat = tid + 256*it)
    const int am  = tid & 127;     // A: m row (constant across it)
    const int akq = tid >> 7;      // A: k-quad base (0..1), +2 per it
    const int bnq = tid & 31;      // B: n-quad (constant)
    const int bk0 = tid >> 5;      // B: k row base (0..7), +8 per it
    const bool bvalid = (p0 + 4 * bnq) < HW;

    const float* wbase = w + (size_t)(r + 8 * am) * UNIT;
    float4 areg[4], breg[4];

    auto LDG = [&](int ch) {
        const float* wa = wbase + ch * KC;
        #pragma unroll
        for (int it = 0; it < 4; it++)
            areg[it] = *(const float4*)(wa + (akq + 2 * it) * 4);
        const int c0 = (r * 128 + ch * KC) & (CIN - 1);
        const float* xbp = xb + (size_t)(c0 + bk0) * HW + p0 + 4 * bnq;
        #pragma unroll
        for (int it = 0; it < 4; it++)
            breg[it] = bvalid ? *(const float4*)(xbp + (size_t)(8 * it) * HW)
                              : make_float4(0.f, 0.f, 0.f, 0.f);
    };

    auto STS = [&](int buf) {
        float* Ab = sm + AS_OFF + buf * KC * PM;
        float* Bb = sm + BS_OFF + buf * KC * PM;
        #pragma unroll
        for (int it = 0; it < 4; it++) {
            const int kq = akq + 2 * it;
            Ab[(kq * 4 + 0) * PM + am] = rna_f(areg[it].x);
            Ab[(kq * 4 + 1) * PM + am] = rna_f(areg[it].y);
            Ab[(kq * 4 + 2) * PM + am] = rna_f(areg[it].z);
            Ab[(kq * 4 + 3) * PM + am] = rna_f(areg[it].w);
        }
        #pragma unroll
        for (int it = 0; it < 4; it++) {
            float4 v = breg[it];
            v.x = rna_f(v.x); v.y = rna_f(v.y);
            v.z = rna_f(v.z); v.w = rna_f(v.w);
            *(float4*)(Bb + (bk0 + 8 * it) * PM + 4 * bnq) = v;
        }
    };

    auto COMPUTE = [&](int buf) {
        const float* Ab = sm + AS_OFF + buf * KC * PM;
        const float* Bb = sm + BS_OFF + buf * KC * PM;
        #pragma unroll
        for (int kk = 0; kk < 4; kk++) {
            const int kb = kk * 8;
            float af[4][4], bf[4][2];
            #pragma unroll
            for (int i = 0; i < 4; i++) {
                const float* lo = Ab + (kb + tg) * PM + m0 + 16 * i + g;
                const float* hi = Ab + (kb + tg + 4) * PM + m0 + 16 * i + g;
                af[i][0] = lo[0];  af[i][1] = lo[8];   // rows g, g+8 @ col tg
                af[i][2] = hi[0];  af[i][3] = hi[8];   // rows g, g+8 @ col tg+4
            }
            #pragma unroll
            for (int j = 0; j < 4; j++) {
                bf[j][0] = Bb[(kb + tg) * PM + n0 + 8 * j + g];
                bf[j][1] = Bb[(kb + tg + 4) * PM + n0 + 8 * j + g];
            }
            #pragma unroll
            for (int i = 0; i < 4; i++)
                #pragma unroll
                for (int j = 0; j < 4; j++)
                    mma8(acc[i][j], af[i], bf[j]);
        }
    };

    // ---- pipelined mainloop: double-buffered k-chunks of 32 ----
    LDG(0);
    STS(0);
    __syncthreads();
    #pragma unroll 1
    for (int ch = 0; ch < NCH; ch++) {
        if (ch + 1 < NCH) LDG(ch + 1);       // global loads overlap compute
        COMPUTE(ch & 1);
        if (ch + 1 < NCH) STS((ch + 1) & 1); // other buffer; prev barrier made it safe
        __syncthreads();
    }

    // ---- epilogue: stage acc -> smem row-major, then coalesced STG ----
    #pragma unroll
    for (int i = 0; i < 4; i++) {
        const int rlo = m0 + 16 * i + g;
        #pragma unroll
        for (int j = 0; j < 4; j++) {
            const int cc = n0 + 8 * j + 2 * tg;
            *(float2*)(sm + rlo * EP + cc)       = make_float2(acc[i][j][0], acc[i][j][1]);
            *(float2*)(sm + (rlo + 8) * EP + cc) = make_float2(acc[i][j][2], acc[i][j][3]);
        }
    }
    __syncthreads();

    float* ob = out + ((size_t)b * 1024 + r) * HW + p0;
    #pragma unroll
    for (int it = 0; it < 16; it++) {
        const int flat = tid + 256 * it;
        const int m = flat >> 5, q = flat & 31;
        if (p0 + 4 * q < HW) {
            const float4 v = *(const float4*)(sm + m * EP + 4 * q);
            *(float4*)(ob + (size_t)(8 * m) * HW + 4 * q) = v;
        }
    }
}

extern "C" void kernel_launch(void* const* d_in, const int* in_sizes, int n_in,
                              void* d_out, int out_size)
{
    const float* x = (const float*)d_in[0];
    const float* w = (const float*)d_in[1];
    float* out = (float*)d_out;

    cudaFuncSetAttribute(scc_mma_kernel,
                         cudaFuncAttributeMaxDynamicSharedMemorySize, SM_BYTES);
    dim3 grid(8, 25, 16);   // r fastest: adjacent groups share x channels in L2
    scc_mma_kernel<<<grid, 256, SM_BYTES>>>(x, w, out);
}

// round 5
// speedup vs baseline: 2.8007x; 1.4232x over previous
#include <cuda_runtime.h>
#include <cstdint>

#define HW    3136
#define CIN   1024
#define NT    224      // spatial tile: 14 * 224 = 3136 exactly
#define KC    32       // k chunk
#define NCH   8

// smem (floats): A: 2 buffers of 4 kk-octets x 128 m x 8 (permuted+swizzled)
//                B: 2 buffers of 32 k x pitch-232 n
#define ASZ   4096                 // floats per A buffer
#define BOFF  (2 * ASZ)            // 8192
#define BPITCH 232
#define BSZ   (KC * BPITCH)        // 7424 floats per B buffer
#define SM_FLOATS (BOFF + 2 * BSZ) // 23040
#define SM_BYTES  (SM_FLOATS * 4)  // 92160

static __device__ __forceinline__ float rna_f(float v) {
    uint32_t o;
    asm("cvt.rna.tf32.f32 %0, %1;" : "=r"(o) : "f"(v));
    return __uint_as_float(o);
}
static __device__ __forceinline__ uint32_t smem_u32(const void* p) {
    uint32_t a;
    asm("{\n\t.reg .u64 t;\n\tcvta.to.shared.u64 t, %1;\n\tcvt.u32.u64 %0, t;\n\t}"
        : "=r"(a) : "l"(p));
    return a;
}
static __device__ __forceinline__ void cp16(uint32_t dst, const void* src) {
    asm volatile("cp.async.cg.shared.global [%0], [%1], 16;" :: "r"(dst), "l"(src));
}
static __device__ __forceinline__ void cp_commit() {
    asm volatile("cp.async.commit_group;");
}
static __device__ __forceinline__ void cp_wait0() {
    asm volatile("cp.async.wait_group 0;");
}

static __device__ __forceinline__ void mma8(float* c, const float* a, const float* b) {
    asm volatile(
        "mma.sync.aligned.m16n8k8.row.col.f32.tf32.tf32.f32 "
        "{%0,%1,%2,%3}, {%4,%5,%6,%7}, {%8,%9}, {%0,%1,%2,%3};"
        : "+f"(c[0]), "+f"(c[1]), "+f"(c[2]), "+f"(c[3])
        : "r"(__float_as_uint(a[0])), "r"(__float_as_uint(a[1])),
          "r"(__float_as_uint(a[2])), "r"(__float_as_uint(a[3])),
          "r"(__float_as_uint(b[0])), "r"(__float_as_uint(b[1])));
}

__global__ __launch_bounds__(256, 1)
void scc_mma_kernel(const float* __restrict__ x,
                    const float* __restrict__ w,
                    float* __restrict__ out)
{
    extern __shared__ float sm[];
    const uint32_t sb = smem_u32(sm);
    const int tid = threadIdx.x;
    const int lid = tid & 31, wid = tid >> 5;
    const int g = lid >> 2, tg = lid & 3;
    const int r  = blockIdx.x;                 // group fastest: L2 x reuse
    const int p0 = blockIdx.y * NT;
    const int b  = blockIdx.z;
    const float* xb = x + (size_t)b * CIN * HW;

    // warp grid 2(M) x 4(N): warp tile 64 x 56
    const int m0 = (wid & 1) * 64;
    const int n0 = (wid >> 1) * 56;

    float acc[4][7][4];
    #pragma unroll
    for (int i = 0; i < 4; i++)
        #pragma unroll
        for (int j = 0; j < 7; j++)
            #pragma unroll
            for (int v = 0; v < 4; v++) acc[i][j][v] = 0.f;

    // ---- A loader role: m row = tid&127, two k-octets (tid>>7)*2 + {0,1} ----
    const int am = tid & 127;
    const int ao = (tid >> 7) * 2;
    const float* wrow = w + (size_t)(r + 8 * am) * 256;
    const int aswz = 2 * ((am >> 2) & 3);      // even XOR, preserves float2 pairs
    float areg[16];

    // ---- B loader role: 7 x 16B cp.async per chunk ----
    // idx = tid + 256*it -> k = idx/56, nq = idx%56
    auto LDG_A = [&](int ch) {
        #pragma unroll
        for (int o = 0; o < 2; o++) {
            *(float4*)&areg[o * 8 + 0] = *(const float4*)(wrow + ch * KC + (ao + o) * 8);
            *(float4*)&areg[o * 8 + 4] = *(const float4*)(wrow + ch * KC + (ao + o) * 8 + 4);
        }
    };
    auto STS_A = [&](int buf) {
        float* Ab = sm + buf * ASZ;
        #pragma unroll
        for (int o = 0; o < 2; o++) {
            float* dst = Ab + (ao + o) * 1024 + am * 8;
            #pragma unroll
            for (int c = 0; c < 4; c++) {
                *(float2*)(dst + ((2 * c) ^ aswz)) =
                    make_float2(rna_f(areg[o * 8 + c]), rna_f(areg[o * 8 + c + 4]));
            }
        }
    };
    auto CPA_B = [&](int ch, int buf) {
        const int c0 = (r * 128 + ch * KC) & (CIN - 1);
        const uint32_t bbase = sb + (BOFF + buf * BSZ) * 4;
        #pragma unroll
        for (int it = 0; it < 7; it++) {
            const int idx = tid + 256 * it;
            const int k = idx / 56, nq = idx % 56;
            cp16(bbase + (k * BPITCH + 4 * nq) * 4,
                 xb + (size_t)(c0 + k) * HW + p0 + 4 * nq);
        }
        cp_commit();
    };

    auto COMPUTE = [&](int buf) {
        const float* Ab = sm + buf * ASZ;
        const float* Bb = sm + BOFF + buf * BSZ;
        #pragma unroll
        for (int kk = 0; kk < 4; kk++) {
            const float* Abk = Ab + kk * 1024;
            const float* Bbk = Bb + kk * 8 * BPITCH;
            float af[4][4], bf[7][2];
            #pragma unroll
            for (int i = 0; i < 4; i++) {
                const int rlo = m0 + 16 * i + g;
                const int rhi = rlo + 8;
                const float2 lo = *(const float2*)(Abk + rlo * 8 + ((2 * tg) ^ (2 * ((rlo >> 2) & 3))));
                const float2 hi = *(const float2*)(Abk + rhi * 8 + ((2 * tg) ^ (2 * ((rhi >> 2) & 3))));
                af[i][0] = lo.x; af[i][1] = hi.x; af[i][2] = lo.y; af[i][3] = hi.y;
            }
            #pragma unroll
            for (int j = 0; j < 7; j++) {
                const int n = n0 + 8 * j + g;
                bf[j][0] = Bbk[tg * BPITCH + n];
                bf[j][1] = Bbk[(tg + 4) * BPITCH + n];
            }
            #pragma unroll
            for (int i = 0; i < 4; i++)
                #pragma unroll
                for (int j = 0; j < 7; j++)
                    mma8(acc[i][j], af[i], bf[j]);
        }
    };

    // ---- pipelined mainloop ----
    CPA_B(0, 0);
    LDG_A(0);
    STS_A(0);
    cp_wait0();
    __syncthreads();

    #pragma unroll 1
    for (int ch = 0; ch < NCH; ch++) {
        const int buf = ch & 1;
        if (ch + 1 < NCH) {
            CPA_B(ch + 1, buf ^ 1);   // async into other buffer, overlaps compute
            LDG_A(ch + 1);
        }
        COMPUTE(buf);
        if (ch + 1 < NCH) {
            STS_A(buf ^ 1);
            cp_wait0();
            __syncthreads();
        }
    }

    // ---- epilogue: direct STG, float2 per fragment half (32B sectors) ----
    float* ob = out + ((size_t)b * 1024 + r) * HW + p0 + n0 + 2 * tg;
    #pragma unroll
    for (int i = 0; i < 4; i++) {
        const int mlo = m0 + 16 * i + g;
        float* prow = ob + (size_t)(8 * mlo) * HW;
        #pragma unroll
        for (int j = 0; j < 7; j++) {
            *(float2*)(prow + 8 * j) = make_float2(acc[i][j][0], acc[i][j][1]);
            *(float2*)(prow + (size_t)64 * HW + 8 * j) = make_float2(acc[i][j][2], acc[i][j][3]);
        }
    }
}

extern "C" void kernel_launch(void* const* d_in, const int* in_sizes, int n_in,
                              void* d_out, int out_size)
{
    const float* x = (const float*)d_in[0];
    const float* w = (const float*)d_in[1];
    float* out = (float*)d_out;

    cudaFuncSetAttribute(scc_mma_kernel,
                         cudaFuncAttributeMaxDynamicSharedMemorySize, SM_BYTES);
    dim3 grid(8, 14, 16);   // 1792 CTAs; r fastest for L2 sharing of x
    scc_mma_kernel<<<grid, 256, SM_BYTES>>>(x, w, out);
}